// round 1
// baseline (speedup 1.0000x reference)
#include <cuda_runtime.h>

// CBOW negative-sampling loss, fused single-pass.
// Shapes (fixed by the problem): B=16384, C=10, K=8, D=128, VOCAB=100000.
// d_in order: contexts[B,C] i32, focus_word[B,K] i32, weight_mask[B,K] f32,
//             labels[B,K] f32, ctx_emb[V,D] f32, neg_emb[V,D] f32.
// d_out: 1 float (batch-mean loss).

#define B_N 16384
#define C_N 10
#define K_N 8
#define D_N 128
#define WARPS_PER_BLOCK 16
#define THREADS (WARPS_PER_BLOCK * 32)
#define NBLOCKS (B_N / WARPS_PER_BLOCK)   // 1024

__device__ float g_partials[NBLOCKS];

__global__ __launch_bounds__(THREADS)
void cbow_loss_kernel(const int*   __restrict__ contexts,
                      const int*   __restrict__ focus,
                      const float* __restrict__ wmask,
                      const float* __restrict__ labels,
                      const float* __restrict__ ctx_emb,
                      const float* __restrict__ neg_emb)
{
    const int warp = threadIdx.x >> 5;
    const int lane = threadIdx.x & 31;
    const int b    = blockIdx.x * WARPS_PER_BLOCK + warp;

    // ---- gather indices (same address per warp -> broadcast loads) ----
    int cidx[C_N];
#pragma unroll
    for (int c = 0; c < C_N; c++) cidx[c] = __ldg(&contexts[b * C_N + c]);

    int fidx[K_N];
#pragma unroll
    for (int k = 0; k < K_N; k++) fidx[k] = __ldg(&focus[b * K_N + k]);

    // ---- sum-pool 10 context rows; lane owns 4 contiguous columns ----
    // All 10 LDG.128 issued independently -> MLP ~ 10 per warp.
    float4 src = make_float4(0.f, 0.f, 0.f, 0.f);
#pragma unroll
    for (int c = 0; c < C_N; c++) {
        const float4 v =
            __ldg(reinterpret_cast<const float4*>(ctx_emb + (size_t)cidx[c] * D_N) + lane);
        src.x += v.x; src.y += v.y; src.z += v.z; src.w += v.w;
    }

    // ---- 8 target dots (independent LDG.128, then butterfly reduce) ----
    float pred[K_N];
#pragma unroll
    for (int k = 0; k < K_N; k++) {
        const float4 t =
            __ldg(reinterpret_cast<const float4*>(neg_emb + (size_t)fidx[k] * D_N) + lane);
        pred[k] = src.x * t.x + src.y * t.y + src.z * t.z + src.w * t.w;
    }
#pragma unroll
    for (int k = 0; k < K_N; k++) {
        float p = pred[k];
#pragma unroll
        for (int off = 16; off; off >>= 1)
            p += __shfl_xor_sync(0xffffffffu, p, off);
        pred[k] = p;   // all lanes hold the full dot
    }

    // ---- weighted BCE-with-logits, per-row renormalization ----
    // logaddexp(0,x) = max(x,0) + log1p(exp(-|x|))   (stable)
    float s_bce = 0.f, s_w = 0.f;
#pragma unroll
    for (int k = 0; k < K_N; k++) {
        const float w = __ldg(&wmask[b * K_N + k]);   // broadcast
        const float y = __ldg(&labels[b * K_N + k]);  // broadcast
        const float x = pred[k];
        const float lae = fmaxf(x, 0.f) + log1pf(__expf(-fabsf(x)));
        s_bce += w * (lae - x * y);
        s_w   += w;
    }
    const float per_row = s_bce / s_w;   // mean_k * K / sum_w == sum_k / sum_w

    // ---- deterministic block partial (fixed summation order) ----
    __shared__ float ws[WARPS_PER_BLOCK];
    if (lane == 0) ws[warp] = per_row;
    __syncthreads();
    if (threadIdx.x == 0) {
        float s = 0.f;
#pragma unroll
        for (int i = 0; i < WARPS_PER_BLOCK; i++) s += ws[i];
        g_partials[blockIdx.x] = s;
    }
}

__global__ __launch_bounds__(NBLOCKS)
void cbow_reduce_kernel(float* __restrict__ out)
{
    const int tid = threadIdx.x;           // blockDim.x == NBLOCKS == 1024
    float v = g_partials[tid];
#pragma unroll
    for (int off = 16; off; off >>= 1)
        v += __shfl_xor_sync(0xffffffffu, v, off);

    __shared__ float s[32];
    if ((tid & 31) == 0) s[tid >> 5] = v;
    __syncthreads();
    if (tid < 32) {
        float x = s[tid];
#pragma unroll
        for (int off = 16; off; off >>= 1)
            x += __shfl_xor_sync(0xffffffffu, x, off);
        if (tid == 0) out[0] = x * (1.0f / (float)B_N);
    }
}

extern "C" void kernel_launch(void* const* d_in, const int* in_sizes, int n_in,
                              void* d_out, int out_size)
{
    const int*   contexts = (const int*)  d_in[0];
    const int*   focus    = (const int*)  d_in[1];
    const float* wmask    = (const float*)d_in[2];
    const float* labels   = (const float*)d_in[3];
    const float* ctx_emb  = (const float*)d_in[4];
    const float* neg_emb  = (const float*)d_in[5];
    float*       out      = (float*)d_out;

    cbow_loss_kernel<<<NBLOCKS, THREADS>>>(contexts, focus, wmask, labels,
                                           ctx_emb, neg_emb);
    cbow_reduce_kernel<<<1, NBLOCKS>>>(out);
}